// round 16
// baseline (speedup 1.0000x reference)
#include <cuda_runtime.h>
#include <math.h>

// ---------------- problem-size maxima (this dataset: N=50000, E=800000) ----
#define NMAX 50000
#define EMAX 800000
#define ETMAX (EMAX + NMAX)
#define SCAN_NB ((NMAX + 1023) / 1024)

// ---------------- scratch (device globals; referenced directly by kernels) --
__device__ float g_h1[(size_t)NMAX * 256];    // layer1 linear output [N,256]
__device__ float g_h2in[(size_t)NMAX * 256];  // layer1 GAT output (+bias,relu)
__device__ float g_h2[(size_t)NMAX * 64];     // layer2 linear output [N,64]
__device__ float g_as1[(size_t)NMAX * 4];
__device__ float g_ad1[(size_t)NMAX * 4];
__device__ float g_as2[NMAX];
__device__ float g_ad2[NMAX];
__device__ int g_counts[NMAX];
__device__ int g_offsets[NMAX + 1];
__device__ int g_cursor[NMAX];
__device__ int g_srcs[ETMAX];
__device__ int g_blocksums[SCAN_NB];
__device__ int g_blockoffs[SCAN_NB];
__device__ int g_is64;  // 1 if edge_index is int64, 0 if int32

#define BUF_H1 0
#define BUF_H2IN 1
#define BUF_H2 2
#define BUF_AS1 3
#define BUF_AD1 4
#define BUF_AS2 5
#define BUF_AD2 6
__device__ __forceinline__ float* fbuf(int id) {
    switch (id) {
        case BUF_H1: return g_h1;
        case BUF_H2IN: return g_h2in;
        case BUF_H2: return g_h2;
        case BUF_AS1: return g_as1;
        case BUF_AD1: return g_ad1;
        case BUF_AS2: return g_as2;
        default: return g_ad2;
    }
}

// ---------------- edge_index dtype detection --------------------------------
__global__ void detect_dtype_kernel(const unsigned int* __restrict__ w) {
    __shared__ int any_nz;
    if (threadIdx.x == 0) any_nz = 0;
    __syncthreads();
    int nz = 0;
    for (int k = threadIdx.x; k < 4096; k += blockDim.x)
        if (w[2 * k + 1] != 0u) nz = 1;
    if (nz) atomicOr(&any_nz, 1);
    __syncthreads();
    if (threadIdx.x == 0) g_is64 = any_nz ? 0 : 1;
}

__device__ __forceinline__ int edge_val(const void* ei, long long idx) {
    if (g_is64) return (int)((const long long*)ei)[idx];
    return ((const int*)ei)[idx];
}

// ---------------- CSR build -------------------------------------------------
__global__ void init_counts_kernel(int N) {
    int i = blockIdx.x * blockDim.x + threadIdx.x;
    if (i < N) g_counts[i] = 1;  // self-loop pre-counted
}

__global__ void hist_kernel(const void* __restrict__ ei, int E, int N) {
    int i = blockIdx.x * blockDim.x + threadIdx.x;
    if (i < E) {
        int dst = edge_val(ei, (long long)E + i);
        if (dst >= 0 && dst < N) atomicAdd(&g_counts[dst], 1);
    }
}

__device__ __forceinline__ int block_incl_scan(int v, int* total) {
    const int lane = threadIdx.x & 31, wid = threadIdx.x >> 5;
    int incl = v;
#pragma unroll
    for (int o = 1; o < 32; o <<= 1) {
        int u = __shfl_up_sync(0xffffffffu, incl, o);
        if (lane >= o) incl += u;
    }
    __shared__ int wsum[32];
    if (lane == 31) wsum[wid] = incl;
    __syncthreads();
    if (wid == 0) {
        int w = wsum[lane];
#pragma unroll
        for (int o = 1; o < 32; o <<= 1) {
            int u = __shfl_up_sync(0xffffffffu, w, o);
            if (lane >= o) w += u;
        }
        wsum[lane] = w;
    }
    __syncthreads();
    if (wid > 0) incl += wsum[wid - 1];
    *total = wsum[31];
    return incl;
}

__global__ void scan_phase1(int N) {
    int i = blockIdx.x * 1024 + threadIdx.x;
    int v = (i < N) ? g_counts[i] : 0;
    int total;
    int incl = block_incl_scan(v, &total);
    if (i < N) g_offsets[i] = incl - v;
    if (threadIdx.x == 1023) g_blocksums[blockIdx.x] = total;
}

__global__ void scan_phase2(int nb, int N) {
    int t = threadIdx.x;
    int v = (t < nb) ? g_blocksums[t] : 0;
    int total;
    int incl = block_incl_scan(v, &total);
    if (t < nb) g_blockoffs[t] = incl - v;
    if (t == 0) g_offsets[N] = total;
}

__global__ void scan_phase3(int N) {
    int i = blockIdx.x * 1024 + threadIdx.x;
    if (i < N) {
        int v = g_offsets[i] + g_blockoffs[blockIdx.x];
        g_offsets[i] = v;
        g_cursor[i] = v;
    }
}

__global__ void scatter_kernel(const void* __restrict__ ei, int E, int N) {
    int i = blockIdx.x * blockDim.x + threadIdx.x;
    int src, dst;
    if (i < E) {
        src = edge_val(ei, i);
        dst = edge_val(ei, (long long)E + i);
    } else if (i < E + N) {
        src = dst = i - E;  // self loop
    } else {
        return;
    }
    if (src < 0 || src >= N || dst < 0 || dst >= N) return;
    int pos = atomicAdd(&g_cursor[dst], 1);
    if (pos >= 0 && pos < ETMAX) g_srcs[pos] = src;
}

// ---------------- tf32x3 tensor-core GEMM + fused alpha epilogue ------------
// C[M,Ntot] = A[M,K] @ B[K,Ntot], BM=128, BN=64 (one head per col-block),
// BK=16, 8 warps (4 m x 2 n), warp tile 32x32, mma.m16n8k8 tf32, 3xTF32 split.
// Epilogue: as_out[node*gridDim.x + blockIdx.x] = sum_c C*a_src, same for ad.

__device__ __forceinline__ void cvt_tf32_pair(float a, float& hi, float& lo) {
    unsigned uh;
    asm("cvt.rna.tf32.f32 %0, %1;" : "=r"(uh) : "f"(a));
    hi = __uint_as_float(uh);
    float l = a - hi;
    unsigned ul;
    asm("cvt.rna.tf32.f32 %0, %1;" : "=r"(ul) : "f"(l));
    lo = __uint_as_float(ul);
}

#define MMA_TF32(d, ax, ay, az, aw, bx, by)                              \
    asm volatile(                                                        \
        "mma.sync.aligned.m16n8k8.row.col.f32.tf32.tf32.f32 "            \
        "{%0,%1,%2,%3}, {%4,%5,%6,%7}, {%8,%9}, {%0,%1,%2,%3};"          \
        : "+f"(d[0]), "+f"(d[1]), "+f"(d[2]), "+f"(d[3])                 \
        : "r"(__float_as_uint(ax)), "r"(__float_as_uint(ay)),            \
          "r"(__float_as_uint(az)), "r"(__float_as_uint(aw)),            \
          "r"(__float_as_uint(bx)), "r"(__float_as_uint(by)))

template <int ASEL, int CSEL, int ASSEL, int ADSEL>
__global__ void gemm_alpha_kernel(const float* __restrict__ Ap,
                                  const float* __restrict__ B,
                                  const float* __restrict__ a_src,
                                  const float* __restrict__ a_dst,
                                  int M, int Ntot, int K) {
    const float* A = (ASEL < 0) ? Ap : fbuf(ASEL);
    float* C = fbuf(CSEL);
    float* as_out = fbuf(ASSEL);
    float* ad_out = fbuf(ADSEL);

    // fragment-packed smem: A: 8 m-tiles x 2 ksteps x (32 thr x 4 regs)
    __shared__ float sAhi[2048], sAlo[2048];
    // B: 8 n-tiles x 2 ksteps x (32 thr x 2 regs)
    __shared__ float sBhi[1024], sBlo[1024];
    __shared__ float s_av[64], s_adv[64];
    __shared__ float s_as[128], s_ad[128];

    const int tid = threadIdx.x;
    const int lane = tid & 31, wid = tid >> 5;
    const int wm = wid >> 1, wn = wid & 1;
    const int row0 = blockIdx.y * 128;
    const int col0 = blockIdx.x * 64;

    if (tid < 64) {
        s_av[tid] = a_src[col0 + tid];
        s_adv[tid] = a_dst[col0 + tid];
    }
    if (tid < 128) {
        s_as[tid] = 0.f;
        s_ad[tid] = 0.f;
    }

    float acc[2][4][4];
#pragma unroll
    for (int mt = 0; mt < 2; mt++)
#pragma unroll
        for (int nt = 0; nt < 4; nt++)
#pragma unroll
            for (int r = 0; r < 4; r++) acc[mt][nt][r] = 0.f;

    for (int k0 = 0; k0 < K; k0 += 16) {
        __syncthreads();
        // A tile 128x16 -> fragment layout (hi/lo)
#pragma unroll
        for (int q = tid; q < 512; q += 256) {
            int r = q >> 2, c4 = (q & 3) << 2;
            float4 v = make_float4(0.f, 0.f, 0.f, 0.f);
            if (row0 + r < M)
                v = *reinterpret_cast<const float4*>(&A[(size_t)(row0 + r) * K + k0 + c4]);
            float vv[4] = {v.x, v.y, v.z, v.w};
            int m_tile = r >> 4, row_in = r & 15;
#pragma unroll
            for (int j = 0; j < 4; j++) {
                int c = c4 + j;
                int kstep = c >> 3, col_in = c & 7;
                int tt = ((row_in & 7) << 2) | (col_in & 3);
                int reg = (row_in >> 3) | ((col_in >> 2) << 1);
                int idx = (((m_tile << 1) | kstep) * 32 + tt) * 4 + reg;
                float hi, lo;
                cvt_tf32_pair(vv[j], hi, lo);
                sAhi[idx] = hi;
                sAlo[idx] = lo;
            }
        }
        // B tile 16x64 -> fragment layout (hi/lo)
#pragma unroll
        for (int q = tid; q < 1024; q += 256) {
            int r = q >> 6, c = q & 63;
            float b = B[(size_t)(k0 + r) * Ntot + col0 + c];
            int kstep = r >> 3, k_in = r & 7;
            int n_tile = c >> 3, n_in = c & 7;
            int tt = (n_in << 2) | (k_in & 3);
            int reg = k_in >> 2;
            int idx = (((n_tile << 1) | kstep) * 32 + tt) * 2 + reg;
            float hi, lo;
            cvt_tf32_pair(b, hi, lo);
            sBhi[idx] = hi;
            sBlo[idx] = lo;
        }
        __syncthreads();
#pragma unroll
        for (int ks = 0; ks < 2; ks++) {
            float4 ahi[2], alo[2];
#pragma unroll
            for (int mt = 0; mt < 2; mt++) {
                int gmt = wm * 2 + mt;
                int base = (((gmt << 1) | ks) * 32 + lane) * 4;
                ahi[mt] = *reinterpret_cast<const float4*>(&sAhi[base]);
                alo[mt] = *reinterpret_cast<const float4*>(&sAlo[base]);
            }
            float2 bhi[4], blo[4];
#pragma unroll
            for (int nt = 0; nt < 4; nt++) {
                int gnt = wn * 4 + nt;
                int base = (((gnt << 1) | ks) * 32 + lane) * 2;
                bhi[nt] = *reinterpret_cast<const float2*>(&sBhi[base]);
                blo[nt] = *reinterpret_cast<const float2*>(&sBlo[base]);
            }
#pragma unroll
            for (int mt = 0; mt < 2; mt++)
#pragma unroll
                for (int nt = 0; nt < 4; nt++) {
                    MMA_TF32(acc[mt][nt], ahi[mt].x, ahi[mt].y, ahi[mt].z, ahi[mt].w,
                             bhi[nt].x, bhi[nt].y);
                    MMA_TF32(acc[mt][nt], ahi[mt].x, ahi[mt].y, ahi[mt].z, ahi[mt].w,
                             blo[nt].x, blo[nt].y);
                    MMA_TF32(acc[mt][nt], alo[mt].x, alo[mt].y, alo[mt].z, alo[mt].w,
                             bhi[nt].x, bhi[nt].y);
                }
        }
    }

    // ---- epilogue: alpha partials (quad reduce -> smem) + C stores ----
#pragma unroll
    for (int mt = 0; mt < 2; mt++) {
        float ps0 = 0.f, pd0 = 0.f, ps1 = 0.f, pd1 = 0.f;
#pragma unroll
        for (int nt = 0; nt < 4; nt++) {
            int cb = wn * 32 + nt * 8 + ((lane & 3) << 1);
            float w0s = s_av[cb], w1s = s_av[cb + 1];
            float w0d = s_adv[cb], w1d = s_adv[cb + 1];
            ps0 += acc[mt][nt][0] * w0s + acc[mt][nt][1] * w1s;
            pd0 += acc[mt][nt][0] * w0d + acc[mt][nt][1] * w1d;
            ps1 += acc[mt][nt][2] * w0s + acc[mt][nt][3] * w1s;
            pd1 += acc[mt][nt][2] * w0d + acc[mt][nt][3] * w1d;
        }
        ps0 += __shfl_xor_sync(0xffffffffu, ps0, 1);
        ps0 += __shfl_xor_sync(0xffffffffu, ps0, 2);
        pd0 += __shfl_xor_sync(0xffffffffu, pd0, 1);
        pd0 += __shfl_xor_sync(0xffffffffu, pd0, 2);
        ps1 += __shfl_xor_sync(0xffffffffu, ps1, 1);
        ps1 += __shfl_xor_sync(0xffffffffu, ps1, 2);
        pd1 += __shfl_xor_sync(0xffffffffu, pd1, 1);
        pd1 += __shfl_xor_sync(0xffffffffu, pd1, 2);
        if ((lane & 3) == 0) {
            int rloc = wm * 32 + mt * 16 + (lane >> 2);
            atomicAdd(&s_as[rloc], ps0);
            atomicAdd(&s_ad[rloc], pd0);
            atomicAdd(&s_as[rloc + 8], ps1);
            atomicAdd(&s_ad[rloc + 8], pd1);
        }
    }
#pragma unroll
    for (int mt = 0; mt < 2; mt++) {
        int r0 = row0 + wm * 32 + mt * 16 + (lane >> 2);
#pragma unroll
        for (int nt = 0; nt < 4; nt++) {
            int cc = col0 + wn * 32 + nt * 8 + ((lane & 3) << 1);
            if (r0 < M)
                *reinterpret_cast<float2*>(&C[(size_t)r0 * Ntot + cc]) =
                    make_float2(acc[mt][nt][0], acc[mt][nt][1]);
            if (r0 + 8 < M)
                *reinterpret_cast<float2*>(&C[(size_t)(r0 + 8) * Ntot + cc]) =
                    make_float2(acc[mt][nt][2], acc[mt][nt][3]);
        }
    }
    __syncthreads();
    if (tid < 128) {
        int node = row0 + tid;
        if (node < M) {
            as_out[(size_t)node * gridDim.x + blockIdx.x] = s_as[tid];
            ad_out[(size_t)node * gridDim.x + blockIdx.x] = s_ad[tid];
        }
    }
}

__device__ __forceinline__ float lrelu(float x) { return x > 0.f ? x : 0.2f * x; }

// ---------------- GAT aggregation: one warp per dst node --------------------
template <int H, int C, int HSEL, int ASSEL, int ADSEL, int OSEL, int DO_RELU>
__global__ void aggregate_kernel(const float* __restrict__ bias, float* __restrict__ outp,
                                 int N) {
    const float* h = fbuf(HSEL);
    const float* as = fbuf(ASSEL);
    const float* ad = fbuf(ADSEL);
    float* out = (OSEL < 0) ? outp : fbuf(OSEL);
    constexpr int HC = H * C, J = HC / 32;
    int w = blockIdx.x * (blockDim.x >> 5) + (threadIdx.x >> 5);
    int lane = threadIdx.x & 31;
    if (w >= N) return;
    const int beg = g_offsets[w], end = g_offsets[w + 1];

    float adv[H];
#pragma unroll
    for (int hh = 0; hh < H; hh++) adv[hh] = ad[(size_t)w * H + hh];

    float m[H];
#pragma unroll
    for (int hh = 0; hh < H; hh++) m[hh] = -1e30f;
    for (int e = beg + lane; e < end; e += 32) {
        int s = g_srcs[e];
#pragma unroll
        for (int hh = 0; hh < H; hh++) {
            float ev = lrelu(as[(size_t)s * H + hh] + adv[hh]);
            m[hh] = fmaxf(m[hh], ev);
        }
    }
#pragma unroll
    for (int hh = 0; hh < H; hh++)
#pragma unroll
        for (int o = 16; o > 0; o >>= 1)
            m[hh] = fmaxf(m[hh], __shfl_xor_sync(0xffffffffu, m[hh], o));

    float sum[H];
#pragma unroll
    for (int hh = 0; hh < H; hh++) sum[hh] = 0.f;
    for (int e = beg + lane; e < end; e += 32) {
        int s = g_srcs[e];
#pragma unroll
        for (int hh = 0; hh < H; hh++) {
            float ev = lrelu(as[(size_t)s * H + hh] + adv[hh]);
            sum[hh] += __expf(ev - m[hh]);
        }
    }
#pragma unroll
    for (int hh = 0; hh < H; hh++)
#pragma unroll
        for (int o = 16; o > 0; o >>= 1)
            sum[hh] += __shfl_xor_sync(0xffffffffu, sum[hh], o);

    float inv[H];
#pragma unroll
    for (int hh = 0; hh < H; hh++) inv[hh] = 1.0f / (sum[hh] + 1e-16f);

    float acc[J];
#pragma unroll
    for (int j = 0; j < J; j++) acc[j] = 0.f;
    for (int e = beg; e < end; e++) {
        int s = g_srcs[e];
        float wv[H];
#pragma unroll
        for (int hh = 0; hh < H; hh++) {
            float ev = lrelu(as[(size_t)s * H + hh] + adv[hh]);
            wv[hh] = __expf(ev - m[hh]) * inv[hh];
        }
        const float* hrow = h + (size_t)s * HC;
#pragma unroll
        for (int j = 0; j < J; j++) {
            int f = lane + 32 * j;
            acc[j] = fmaf(wv[f / C], hrow[f], acc[j]);
        }
    }
#pragma unroll
    for (int j = 0; j < J; j++) {
        int f = lane + 32 * j;
        float v = acc[j] + bias[f];
        if (DO_RELU) v = fmaxf(v, 0.f);
        out[(size_t)w * HC + f] = v;
    }
}

// ---------------- launcher: kernel launches ONLY -----------------------------
extern "C" void kernel_launch(void* const* d_in, const int* in_sizes, int n_in,
                              void* d_out, int out_size) {
    const float* x = (const float*)d_in[0];     // [N,128]
    const void* ei = d_in[1];                   // [2,E] int64 or int32
    const float* W1 = (const float*)d_in[2];    // [128,256]
    const float* a_s1 = (const float*)d_in[3];  // [4,64]
    const float* a_d1 = (const float*)d_in[4];  // [4,64]
    const float* b1 = (const float*)d_in[5];    // [256]
    const float* W2 = (const float*)d_in[6];    // [256,64]
    const float* a_s2 = (const float*)d_in[7];  // [1,64]
    const float* a_d2 = (const float*)d_in[8];  // [1,64]
    const float* b2 = (const float*)d_in[9];    // [64]
    float* out = (float*)d_out;                 // [N,64]

    const int N = in_sizes[0] / 128;
    const int E = in_sizes[1] / 2;
    const int nb = (N + 1023) / 1024;

    // CSR by dst (self loops included)
    detect_dtype_kernel<<<1, 256>>>((const unsigned int*)ei);
    init_counts_kernel<<<(N + 255) / 256, 256>>>(N);
    hist_kernel<<<(E + 255) / 256, 256>>>(ei, E, N);
    scan_phase1<<<nb, 1024>>>(N);
    scan_phase2<<<1, 1024>>>(nb, N);
    scan_phase3<<<nb, 1024>>>(N);
    scatter_kernel<<<(E + N + 255) / 256, 256>>>(ei, E, N);

    const int warp_blocks = (N + 7) / 8;
    const int mrows = (N + 127) / 128;

    // Layer 1: h1 = x@W1 (+fused as1/ad1) ; aggregate(+bias,relu) -> h2in
    gemm_alpha_kernel<-1, BUF_H1, BUF_AS1, BUF_AD1>
        <<<dim3(4, mrows), 256>>>(x, W1, a_s1, a_d1, N, 256, 128);
    aggregate_kernel<4, 64, BUF_H1, BUF_AS1, BUF_AD1, BUF_H2IN, 1>
        <<<warp_blocks, 256>>>(b1, nullptr, N);

    // Layer 2: h2 = h2in@W2 (+fused as2/ad2) ; aggregate(+bias) -> out
    gemm_alpha_kernel<BUF_H2IN, BUF_H2, BUF_AS2, BUF_AD2>
        <<<dim3(1, mrows), 256>>>(nullptr, W2, a_s2, a_d2, N, 64, 256);
    aggregate_kernel<1, 64, BUF_H2, BUF_AS2, BUF_AD2, -1, 0>
        <<<warp_blocks, 256>>>(b2, out, N);
}

// round 17
// speedup vs baseline: 1.0045x; 1.0045x over previous
#include <cuda_runtime.h>
#include <math.h>

// ---------------- problem-size maxima (this dataset: N=50000, E=800000) ----
#define NMAX 50000
#define EMAX 800000
#define ETMAX (EMAX + NMAX)
#define SCAN_NB ((NMAX + 1023) / 1024)

// ---------------- scratch (device globals; referenced directly by kernels) --
__device__ float g_h1[(size_t)NMAX * 256];    // layer1 linear output [N,256]
__device__ float g_h2in[(size_t)NMAX * 256];  // layer1 GAT output (+bias,relu)
__device__ float g_h2[(size_t)NMAX * 64];     // layer2 linear output [N,64]
__device__ float g_as1[(size_t)NMAX * 4];
__device__ float g_ad1[(size_t)NMAX * 4];
__device__ float g_as2[NMAX];
__device__ float g_ad2[NMAX];
__device__ int g_counts[NMAX];
__device__ int g_offsets[NMAX + 1];
__device__ int g_cursor[NMAX];
__device__ int g_srcs[ETMAX];
__device__ int g_blocksums[SCAN_NB];
__device__ int g_blockoffs[SCAN_NB];
__device__ int g_is64;  // 1 if edge_index is int64, 0 if int32

#define BUF_H1 0
#define BUF_H2IN 1
#define BUF_H2 2
#define BUF_AS1 3
#define BUF_AD1 4
#define BUF_AS2 5
#define BUF_AD2 6
__device__ __forceinline__ float* fbuf(int id) {
    switch (id) {
        case BUF_H1: return g_h1;
        case BUF_H2IN: return g_h2in;
        case BUF_H2: return g_h2;
        case BUF_AS1: return g_as1;
        case BUF_AD1: return g_ad1;
        case BUF_AS2: return g_as2;
        default: return g_ad2;
    }
}

// ---------------- edge_index dtype detection --------------------------------
__global__ void detect_dtype_kernel(const unsigned int* __restrict__ w) {
    __shared__ int any_nz;
    if (threadIdx.x == 0) any_nz = 0;
    __syncthreads();
    int nz = 0;
    for (int k = threadIdx.x; k < 4096; k += blockDim.x)
        if (w[2 * k + 1] != 0u) nz = 1;
    if (nz) atomicOr(&any_nz, 1);
    __syncthreads();
    if (threadIdx.x == 0) g_is64 = any_nz ? 0 : 1;
}

__device__ __forceinline__ int edge_val(const void* ei, long long idx) {
    if (g_is64) return (int)((const long long*)ei)[idx];
    return ((const int*)ei)[idx];
}

// ---------------- CSR build -------------------------------------------------
__global__ void init_counts_kernel(int N) {
    int i = blockIdx.x * blockDim.x + threadIdx.x;
    if (i < N) g_counts[i] = 1;  // self-loop pre-counted
}

__global__ void hist_kernel(const void* __restrict__ ei, int E, int N) {
    int i = blockIdx.x * blockDim.x + threadIdx.x;
    if (i < E) {
        int dst = edge_val(ei, (long long)E + i);
        if (dst >= 0 && dst < N) atomicAdd(&g_counts[dst], 1);
    }
}

__device__ __forceinline__ int block_incl_scan(int v, int* total) {
    const int lane = threadIdx.x & 31, wid = threadIdx.x >> 5;
    int incl = v;
#pragma unroll
    for (int o = 1; o < 32; o <<= 1) {
        int u = __shfl_up_sync(0xffffffffu, incl, o);
        if (lane >= o) incl += u;
    }
    __shared__ int wsum[32];
    if (lane == 31) wsum[wid] = incl;
    __syncthreads();
    if (wid == 0) {
        int w = wsum[lane];
#pragma unroll
        for (int o = 1; o < 32; o <<= 1) {
            int u = __shfl_up_sync(0xffffffffu, w, o);
            if (lane >= o) w += u;
        }
        wsum[lane] = w;
    }
    __syncthreads();
    if (wid > 0) incl += wsum[wid - 1];
    *total = wsum[31];
    return incl;
}

__global__ void scan_phase1(int N) {
    int i = blockIdx.x * 1024 + threadIdx.x;
    int v = (i < N) ? g_counts[i] : 0;
    int total;
    int incl = block_incl_scan(v, &total);
    if (i < N) g_offsets[i] = incl - v;
    if (threadIdx.x == 1023) g_blocksums[blockIdx.x] = total;
}

__global__ void scan_phase2(int nb, int N) {
    int t = threadIdx.x;
    int v = (t < nb) ? g_blocksums[t] : 0;
    int total;
    int incl = block_incl_scan(v, &total);
    if (t < nb) g_blockoffs[t] = incl - v;
    if (t == 0) g_offsets[N] = total;
}

__global__ void scan_phase3(int N) {
    int i = blockIdx.x * 1024 + threadIdx.x;
    if (i < N) {
        int v = g_offsets[i] + g_blockoffs[blockIdx.x];
        g_offsets[i] = v;
        g_cursor[i] = v;
    }
}

__global__ void scatter_kernel(const void* __restrict__ ei, int E, int N) {
    int i = blockIdx.x * blockDim.x + threadIdx.x;
    int src, dst;
    if (i < E) {
        src = edge_val(ei, i);
        dst = edge_val(ei, (long long)E + i);
    } else if (i < E + N) {
        src = dst = i - E;  // self loop
    } else {
        return;
    }
    if (src < 0 || src >= N || dst < 0 || dst >= N) return;
    int pos = atomicAdd(&g_cursor[dst], 1);
    if (pos >= 0 && pos < ETMAX) g_srcs[pos] = src;
}

// ---------------- tf32x3 tensor-core GEMM + fused alpha epilogue ------------
// C[M,Ntot] = A[M,K] @ B[K,Ntot], BM=128, BN=64 (one head per col-block),
// BK=16, 8 warps (4 m x 2 n), warp tile 32x32, mma.m16n8k8 tf32, 3xTF32 split.
// Epilogue: as_out[node*gridDim.x + blockIdx.x] = sum_c C*a_src, same for ad.

__device__ __forceinline__ void cvt_tf32_pair(float a, float& hi, float& lo) {
    unsigned uh;
    asm("cvt.rna.tf32.f32 %0, %1;" : "=r"(uh) : "f"(a));
    hi = __uint_as_float(uh);
    float l = a - hi;
    unsigned ul;
    asm("cvt.rna.tf32.f32 %0, %1;" : "=r"(ul) : "f"(l));
    lo = __uint_as_float(ul);
}

#define MMA_TF32(d, ax, ay, az, aw, bx, by)                              \
    asm volatile(                                                        \
        "mma.sync.aligned.m16n8k8.row.col.f32.tf32.tf32.f32 "            \
        "{%0,%1,%2,%3}, {%4,%5,%6,%7}, {%8,%9}, {%0,%1,%2,%3};"          \
        : "+f"(d[0]), "+f"(d[1]), "+f"(d[2]), "+f"(d[3])                 \
        : "r"(__float_as_uint(ax)), "r"(__float_as_uint(ay)),            \
          "r"(__float_as_uint(az)), "r"(__float_as_uint(aw)),            \
          "r"(__float_as_uint(bx)), "r"(__float_as_uint(by)))

template <int ASEL, int CSEL, int ASSEL, int ADSEL>
__global__ void gemm_alpha_kernel(const float* __restrict__ Ap,
                                  const float* __restrict__ B,
                                  const float* __restrict__ a_src,
                                  const float* __restrict__ a_dst,
                                  int M, int Ntot, int K) {
    const float* A = (ASEL < 0) ? Ap : fbuf(ASEL);
    float* C = fbuf(CSEL);
    float* as_out = fbuf(ASSEL);
    float* ad_out = fbuf(ADSEL);

    // fragment-packed smem: A: 8 m-tiles x 2 ksteps x (32 thr x 4 regs)
    __shared__ float sAhi[2048], sAlo[2048];
    // B: 8 n-tiles x 2 ksteps x (32 thr x 2 regs)
    __shared__ float sBhi[1024], sBlo[1024];
    __shared__ float s_av[64], s_adv[64];
    __shared__ float s_as[128], s_ad[128];

    const int tid = threadIdx.x;
    const int lane = tid & 31, wid = tid >> 5;
    const int wm = wid >> 1, wn = wid & 1;
    const int row0 = blockIdx.y * 128;
    const int col0 = blockIdx.x * 64;

    if (tid < 64) {
        s_av[tid] = a_src[col0 + tid];
        s_adv[tid] = a_dst[col0 + tid];
    }
    if (tid < 128) {
        s_as[tid] = 0.f;
        s_ad[tid] = 0.f;
    }

    float acc[2][4][4];
#pragma unroll
    for (int mt = 0; mt < 2; mt++)
#pragma unroll
        for (int nt = 0; nt < 4; nt++)
#pragma unroll
            for (int r = 0; r < 4; r++) acc[mt][nt][r] = 0.f;

    for (int k0 = 0; k0 < K; k0 += 16) {
        __syncthreads();
        // A tile 128x16 -> fragment layout (hi/lo)
#pragma unroll
        for (int q = tid; q < 512; q += 256) {
            int r = q >> 2, c4 = (q & 3) << 2;
            float4 v = make_float4(0.f, 0.f, 0.f, 0.f);
            if (row0 + r < M)
                v = *reinterpret_cast<const float4*>(&A[(size_t)(row0 + r) * K + k0 + c4]);
            float vv[4] = {v.x, v.y, v.z, v.w};
            int m_tile = r >> 4, row_in = r & 15;
#pragma unroll
            for (int j = 0; j < 4; j++) {
                int c = c4 + j;
                int kstep = c >> 3, col_in = c & 7;
                int tt = ((row_in & 7) << 2) | (col_in & 3);
                int reg = (row_in >> 3) | ((col_in >> 2) << 1);
                int idx = (((m_tile << 1) | kstep) * 32 + tt) * 4 + reg;
                float hi, lo;
                cvt_tf32_pair(vv[j], hi, lo);
                sAhi[idx] = hi;
                sAlo[idx] = lo;
            }
        }
        // B tile 16x64 -> fragment layout (hi/lo)
#pragma unroll
        for (int q = tid; q < 1024; q += 256) {
            int r = q >> 6, c = q & 63;
            float b = B[(size_t)(k0 + r) * Ntot + col0 + c];
            int kstep = r >> 3, k_in = r & 7;
            int n_tile = c >> 3, n_in = c & 7;
            int tt = (n_in << 2) | (k_in & 3);
            int reg = k_in >> 2;
            int idx = (((n_tile << 1) | kstep) * 32 + tt) * 2 + reg;
            float hi, lo;
            cvt_tf32_pair(b, hi, lo);
            sBhi[idx] = hi;
            sBlo[idx] = lo;
        }
        __syncthreads();
#pragma unroll
        for (int ks = 0; ks < 2; ks++) {
            float4 ahi[2], alo[2];
#pragma unroll
            for (int mt = 0; mt < 2; mt++) {
                int gmt = wm * 2 + mt;
                int base = (((gmt << 1) | ks) * 32 + lane) * 4;
                ahi[mt] = *reinterpret_cast<const float4*>(&sAhi[base]);
                alo[mt] = *reinterpret_cast<const float4*>(&sAlo[base]);
            }
            float2 bhi[4], blo[4];
#pragma unroll
            for (int nt = 0; nt < 4; nt++) {
                int gnt = wn * 4 + nt;
                int base = (((gnt << 1) | ks) * 32 + lane) * 2;
                bhi[nt] = *reinterpret_cast<const float2*>(&sBhi[base]);
                blo[nt] = *reinterpret_cast<const float2*>(&sBlo[base]);
            }
#pragma unroll
            for (int mt = 0; mt < 2; mt++)
#pragma unroll
                for (int nt = 0; nt < 4; nt++) {
                    MMA_TF32(acc[mt][nt], ahi[mt].x, ahi[mt].y, ahi[mt].z, ahi[mt].w,
                             bhi[nt].x, bhi[nt].y);
                    MMA_TF32(acc[mt][nt], ahi[mt].x, ahi[mt].y, ahi[mt].z, ahi[mt].w,
                             blo[nt].x, blo[nt].y);
                    MMA_TF32(acc[mt][nt], alo[mt].x, alo[mt].y, alo[mt].z, alo[mt].w,
                             bhi[nt].x, bhi[nt].y);
                }
        }
    }

    // ---- epilogue: alpha partials (quad reduce -> smem) + C stores ----
#pragma unroll
    for (int mt = 0; mt < 2; mt++) {
        float ps0 = 0.f, pd0 = 0.f, ps1 = 0.f, pd1 = 0.f;
#pragma unroll
        for (int nt = 0; nt < 4; nt++) {
            int cb = wn * 32 + nt * 8 + ((lane & 3) << 1);
            float w0s = s_av[cb], w1s = s_av[cb + 1];
            float w0d = s_adv[cb], w1d = s_adv[cb + 1];
            ps0 += acc[mt][nt][0] * w0s + acc[mt][nt][1] * w1s;
            pd0 += acc[mt][nt][0] * w0d + acc[mt][nt][1] * w1d;
            ps1 += acc[mt][nt][2] * w0s + acc[mt][nt][3] * w1s;
            pd1 += acc[mt][nt][2] * w0d + acc[mt][nt][3] * w1d;
        }
        ps0 += __shfl_xor_sync(0xffffffffu, ps0, 1);
        ps0 += __shfl_xor_sync(0xffffffffu, ps0, 2);
        pd0 += __shfl_xor_sync(0xffffffffu, pd0, 1);
        pd0 += __shfl_xor_sync(0xffffffffu, pd0, 2);
        ps1 += __shfl_xor_sync(0xffffffffu, ps1, 1);
        ps1 += __shfl_xor_sync(0xffffffffu, ps1, 2);
        pd1 += __shfl_xor_sync(0xffffffffu, pd1, 1);
        pd1 += __shfl_xor_sync(0xffffffffu, pd1, 2);
        if ((lane & 3) == 0) {
            int rloc = wm * 32 + mt * 16 + (lane >> 2);
            atomicAdd(&s_as[rloc], ps0);
            atomicAdd(&s_ad[rloc], pd0);
            atomicAdd(&s_as[rloc + 8], ps1);
            atomicAdd(&s_ad[rloc + 8], pd1);
        }
    }
#pragma unroll
    for (int mt = 0; mt < 2; mt++) {
        int r0 = row0 + wm * 32 + mt * 16 + (lane >> 2);
#pragma unroll
        for (int nt = 0; nt < 4; nt++) {
            int cc = col0 + wn * 32 + nt * 8 + ((lane & 3) << 1);
            if (r0 < M)
                *reinterpret_cast<float2*>(&C[(size_t)r0 * Ntot + cc]) =
                    make_float2(acc[mt][nt][0], acc[mt][nt][1]);
            if (r0 + 8 < M)
                *reinterpret_cast<float2*>(&C[(size_t)(r0 + 8) * Ntot + cc]) =
                    make_float2(acc[mt][nt][2], acc[mt][nt][3]);
        }
    }
    __syncthreads();
    if (tid < 128) {
        int node = row0 + tid;
        if (node < M) {
            as_out[(size_t)node * gridDim.x + blockIdx.x] = s_as[tid];
            ad_out[(size_t)node * gridDim.x + blockIdx.x] = s_ad[tid];
        }
    }
}

__device__ __forceinline__ float lrelu(float x) { return x > 0.f ? x : 0.2f * x; }

// ---------------- GAT aggregation: one warp per dst node --------------------
template <int H, int C, int HSEL, int ASSEL, int ADSEL, int OSEL, int DO_RELU>
__global__ void aggregate_kernel(const float* __restrict__ bias, float* __restrict__ outp,
                                 int N) {
    const float* h = fbuf(HSEL);
    const float* as = fbuf(ASSEL);
    const float* ad = fbuf(ADSEL);
    float* out = (OSEL < 0) ? outp : fbuf(OSEL);
    constexpr int HC = H * C, J = HC / 32;
    int w = blockIdx.x * (blockDim.x >> 5) + (threadIdx.x >> 5);
    int lane = threadIdx.x & 31;
    if (w >= N) return;
    const int beg = g_offsets[w], end = g_offsets[w + 1];

    float adv[H];
#pragma unroll
    for (int hh = 0; hh < H; hh++) adv[hh] = ad[(size_t)w * H + hh];

    float m[H];
#pragma unroll
    for (int hh = 0; hh < H; hh++) m[hh] = -1e30f;
    for (int e = beg + lane; e < end; e += 32) {
        int s = g_srcs[e];
#pragma unroll
        for (int hh = 0; hh < H; hh++) {
            float ev = lrelu(as[(size_t)s * H + hh] + adv[hh]);
            m[hh] = fmaxf(m[hh], ev);
        }
    }
#pragma unroll
    for (int hh = 0; hh < H; hh++)
#pragma unroll
        for (int o = 16; o > 0; o >>= 1)
            m[hh] = fmaxf(m[hh], __shfl_xor_sync(0xffffffffu, m[hh], o));

    float sum[H];
#pragma unroll
    for (int hh = 0; hh < H; hh++) sum[hh] = 0.f;
    for (int e = beg + lane; e < end; e += 32) {
        int s = g_srcs[e];
#pragma unroll
        for (int hh = 0; hh < H; hh++) {
            float ev = lrelu(as[(size_t)s * H + hh] + adv[hh]);
            sum[hh] += __expf(ev - m[hh]);
        }
    }
#pragma unroll
    for (int hh = 0; hh < H; hh++)
#pragma unroll
        for (int o = 16; o > 0; o >>= 1)
            sum[hh] += __shfl_xor_sync(0xffffffffu, sum[hh], o);

    float inv[H];
#pragma unroll
    for (int hh = 0; hh < H; hh++) inv[hh] = 1.0f / (sum[hh] + 1e-16f);

    float acc[J];
#pragma unroll
    for (int j = 0; j < J; j++) acc[j] = 0.f;
    for (int e = beg; e < end; e++) {
        int s = g_srcs[e];
        float wv[H];
#pragma unroll
        for (int hh = 0; hh < H; hh++) {
            float ev = lrelu(as[(size_t)s * H + hh] + adv[hh]);
            wv[hh] = __expf(ev - m[hh]) * inv[hh];
        }
        const float* hrow = h + (size_t)s * HC;
#pragma unroll
        for (int j = 0; j < J; j++) {
            int f = lane + 32 * j;
            acc[j] = fmaf(wv[f / C], hrow[f], acc[j]);
        }
    }
#pragma unroll
    for (int j = 0; j < J; j++) {
        int f = lane + 32 * j;
        float v = acc[j] + bias[f];
        if (DO_RELU) v = fmaxf(v, 0.f);
        out[(size_t)w * HC + f] = v;
    }
}

// ---------------- launcher: kernel launches ONLY -----------------------------
extern "C" void kernel_launch(void* const* d_in, const int* in_sizes, int n_in,
                              void* d_out, int out_size) {
    const float* x = (const float*)d_in[0];     // [N,128]
    const void* ei = d_in[1];                   // [2,E] int64 or int32
    const float* W1 = (const float*)d_in[2];    // [128,256]
    const float* a_s1 = (const float*)d_in[3];  // [4,64]
    const float* a_d1 = (const float*)d_in[4];  // [4,64]
    const float* b1 = (const float*)d_in[5];    // [256]
    const float* W2 = (const float*)d_in[6];    // [256,64]
    const float* a_s2 = (const float*)d_in[7];  // [1,64]
    const float* a_d2 = (const float*)d_in[8];  // [1,64]
    const float* b2 = (const float*)d_in[9];    // [64]
    float* out = (float*)d_out;                 // [N,64]

    const int N = in_sizes[0] / 128;
    const int E = in_sizes[1] / 2;
    const int nb = (N + 1023) / 1024;

    // CSR by dst (self loops included)
    detect_dtype_kernel<<<1, 256>>>((const unsigned int*)ei);
    init_counts_kernel<<<(N + 255) / 256, 256>>>(N);
    hist_kernel<<<(E + 255) / 256, 256>>>(ei, E, N);
    scan_phase1<<<nb, 1024>>>(N);
    scan_phase2<<<1, 1024>>>(nb, N);
    scan_phase3<<<nb, 1024>>>(N);
    scatter_kernel<<<(E + N + 255) / 256, 256>>>(ei, E, N);

    const int warp_blocks = (N + 7) / 8;
    const int mrows = (N + 127) / 128;

    // Layer 1: h1 = x@W1 (+fused as1/ad1) ; aggregate(+bias,relu) -> h2in
    gemm_alpha_kernel<-1, BUF_H1, BUF_AS1, BUF_AD1>
        <<<dim3(4, mrows), 256>>>(x, W1, a_s1, a_d1, N, 256, 128);
    aggregate_kernel<4, 64, BUF_H1, BUF_AS1, BUF_AD1, BUF_H2IN, 1>
        <<<warp_blocks, 256>>>(b1, nullptr, N);

    // Layer 2: h2 = h2in@W2 (+fused as2/ad2) ; aggregate(+bias) -> out
    gemm_alpha_kernel<BUF_H2IN, BUF_H2, BUF_AS2, BUF_AD2>
        <<<dim3(1, mrows), 256>>>(nullptr, W2, a_s2, a_d2, N, 64, 256);
    aggregate_kernel<1, 64, BUF_H2, BUF_AS2, BUF_AD2, -1, 0>
        <<<warp_blocks, 256>>>(b2, out, N);
}